// round 15
// baseline (speedup 1.0000x reference)
#include <cuda_runtime.h>
#include <cuda_bf16.h>
#include <cuda_fp16.h>
#include <cstdint>
#include <stdint.h>
#include <math.h>

// ---------------- problem constants ----------------
#define HP    256
#define WPIX  512
#define P_IMG 131072          // HP*WPIX  (low-res pixels)
#define NPTS  1179648         // P_IMG*9  (splat points)
#define H_OUT 512
#define W_OUT 1024
#define HW    524288          // H_OUT*W_OUT
#define C_IN  128
#define C_OUT 64
#define VB    75497472        // NPTS*64  (vals2 elements per batch)
#define MAXREC 24

// ---------------- device scratch (allocation-free) ----------------
__device__ __half g_vals2h[(size_t)2 * VB];        // [b][p*9+tap][64]  fp16
__device__ int2  g_rec[(size_t)HW * MAXREC];       // splat record table
__device__ int   g_cnt[HW];
__device__ __nv_bfloat16 g_wh[2 * 576 * 128];      // folded weights hi (row m = tap*64+o)
__device__ __nv_bfloat16 g_wl[2 * 576 * 128];      // folded weights lo
__device__ __nv_bfloat16 g_xh[(size_t)2 * C_IN * P_IMG];  // x split hi
__device__ __nv_bfloat16 g_xl[(size_t)2 * C_IN * P_IMG];  // x split lo
__device__ float g_vbias[2 * 576];
__device__ float g_bias2[64];
__device__ float g_gn1sum[64];                     // [b][32 groups]
__device__ float g_gn1ssq[64];
__device__ float g_gn2sum[128];                    // [b][64 ch]
__device__ float g_gn2ssq[128];

// ---------------- K0: zero counters/stats ----------------
__global__ void k_zero() {
    int i = blockIdx.x * 256 + threadIdx.x;
    if (i < HW) g_cnt[i] = 0;
    if (i < 64)  { g_gn1sum[i] = 0.f; g_gn1ssq[i] = 0.f; }
    if (i < 128) { g_gn2sum[i] = 0.f; g_gn2ssq[i] = 0.f; }
}

// ---------------- K1: GroupNorm-1 stats + bf16 hi/lo split (fused) --------
__global__ __launch_bounds__(256) void k_gn1split(const float* __restrict__ x) {
    int bc = blockIdx.x;                 // b*128 + c
    size_t rowoff = (size_t)bc * P_IMG + (size_t)blockIdx.y * 32768;
    const float4* p = (const float4*)(x + rowoff);
    __nv_bfloat162* ph = (__nv_bfloat162*)(g_xh + rowoff);
    __nv_bfloat162* pl = (__nv_bfloat162*)(g_xl + rowoff);
    float s = 0.f, q = 0.f;
    for (int i = threadIdx.x; i < 8192; i += 256) {
        float4 v = p[i];
        s += v.x + v.y + v.z + v.w;
        q += v.x * v.x + v.y * v.y + v.z * v.z + v.w * v.w;
        __nv_bfloat16 hx = __float2bfloat16(v.x);
        __nv_bfloat16 hy = __float2bfloat16(v.y);
        __nv_bfloat16 hz = __float2bfloat16(v.z);
        __nv_bfloat16 hw = __float2bfloat16(v.w);
        ph[2 * i]     = __halves2bfloat162(hx, hy);
        ph[2 * i + 1] = __halves2bfloat162(hz, hw);
        pl[2 * i]     = __halves2bfloat162(__float2bfloat16(v.x - __bfloat162float(hx)),
                                           __float2bfloat16(v.y - __bfloat162float(hy)));
        pl[2 * i + 1] = __halves2bfloat162(__float2bfloat16(v.z - __bfloat162float(hz)),
                                           __float2bfloat16(v.w - __bfloat162float(hw)));
    }
    __shared__ float sh1[8], sh2[8];
    for (int off = 16; off; off >>= 1) {
        s += __shfl_down_sync(0xffffffffu, s, off);
        q += __shfl_down_sync(0xffffffffu, q, off);
    }
    int lane = threadIdx.x & 31, warp = threadIdx.x >> 5;
    if (lane == 0) { sh1[warp] = s; sh2[warp] = q; }
    __syncthreads();
    if (threadIdx.x == 0) {
        float S = 0.f, Q = 0.f;
        for (int i = 0; i < 8; i++) { S += sh1[i]; Q += sh2[i]; }
        int b = bc >> 7, g = (bc & 127) >> 2;     // 4 channels per group
        atomicAdd(&g_gn1sum[b * 32 + g], S);
        atomicAdd(&g_gn1ssq[b * 32 + g], Q);
    }
}

// ---------------- K2: fold w_post . w_conv . GN1 into wh/wl/vbias/bias2 ----
__global__ __launch_bounds__(128) void k_prep(const float* __restrict__ w_conv,
                                              const float* __restrict__ w_post,
                                              const float* __restrict__ gamma1,
                                              const float* __restrict__ beta1,
                                              const float* __restrict__ splat_bias,
                                              const float* __restrict__ b_post) {
    int m = blockIdx.x;                  // tap-major row: m = tap*64 + o
    int tap = m >> 6, o = m & 63;
    int c = threadIdx.x;                 // 0..127
    __shared__ float sp[64];
    __shared__ float red[128];
    if (c < 64) sp[c] = w_post[o * 64 + c];
    __syncthreads();
    float w2 = 0.f;
    #pragma unroll 8
    for (int k = 0; k < 64; k++) w2 += sp[k] * w_conv[(k * 9 + tap) * 128 + c];

    float ga = gamma1[c], be = beta1[c];
    int g = c >> 2;
    for (int b = 0; b < 2; b++) {
        float su = g_gn1sum[b * 32 + g], sq = g_gn1ssq[b * 32 + g];
        float mu  = su * (1.0f / 524288.0f);
        float var = sq * (1.0f / 524288.0f) - mu * mu;
        float rs  = rsqrtf(var + 1e-5f);
        float sc  = rs * ga;
        float sh  = be - mu * sc;
        float wsv = w2 * sc;
        __nv_bfloat16 h = __float2bfloat16(wsv);
        g_wh[((size_t)b * 576 + m) * 128 + c] = h;
        g_wl[((size_t)b * 576 + m) * 128 + c] =
            __float2bfloat16(wsv - __bfloat162float(h));
        red[c] = w2 * sh;
        __syncthreads();
        for (int s = 64; s > 0; s >>= 1) { if (c < s) red[c] += red[c + s]; __syncthreads(); }
        if (c == 0) g_vbias[b * 576 + m] = red[0];
        __syncthreads();
    }
    if (tap == 0) {
        red[c] = (c < 64) ? sp[c] * splat_bias[c] : 0.f;
        __syncthreads();
        for (int s = 64; s > 0; s >>= 1) { if (c < s) red[c] += red[c + s]; __syncthreads(); }
        if (c == 0) g_bias2[o] = red[0] + b_post[o];
    }
}

// ---------------- tensor-core / async helpers ----------------
__device__ __forceinline__ void ldsm_x4(uint32_t* r, const void* p) {
    uint32_t a = (uint32_t)__cvta_generic_to_shared(p);
    asm volatile("ldmatrix.sync.aligned.m8n8.x4.shared.b16 {%0,%1,%2,%3}, [%4];"
        : "=r"(r[0]), "=r"(r[1]), "=r"(r[2]), "=r"(r[3]) : "r"(a));
}
__device__ __forceinline__ void ldsm_x4t(uint32_t* r, const void* p) {
    uint32_t a = (uint32_t)__cvta_generic_to_shared(p);
    asm volatile("ldmatrix.sync.aligned.m8n8.x4.trans.shared.b16 {%0,%1,%2,%3}, [%4];"
        : "=r"(r[0]), "=r"(r[1]), "=r"(r[2]), "=r"(r[3]) : "r"(a));
}
__device__ __forceinline__ void mma_bf16(float* c, const uint32_t* a,
                                         uint32_t b0, uint32_t b1) {
    asm volatile("mma.sync.aligned.m16n8k16.row.col.f32.bf16.bf16.f32 "
        "{%0,%1,%2,%3}, {%4,%5,%6,%7}, {%8,%9}, {%0,%1,%2,%3};"
        : "+f"(c[0]), "+f"(c[1]), "+f"(c[2]), "+f"(c[3])
        : "r"(a[0]), "r"(a[1]), "r"(a[2]), "r"(a[3]), "r"(b0), "r"(b1));
}
__device__ __forceinline__ void cp16(void* dst, const void* src) {
    uint32_t d = (uint32_t)__cvta_generic_to_shared(dst);
    asm volatile("cp.async.cg.shared.global [%0], [%1], 16;" :: "r"(d), "l"(src));
}
#define CP_COMMIT() asm volatile("cp.async.commit_group;")
#define CP_WAIT1()  asm volatile("cp.async.wait_group 1;")

// ---------------- K3: pipelined tensor-core GEMM (split bf16, 3-term) ------
// A (64x128 hi+lo) resident in smem for the whole K; 3-stage B ring;
// ONE barrier + one wait_group per k-chunk.
#define AFH_OFF 0u
#define AFL_OFF 17408u
#define BST_OFF 34816u
#define BST_SZ  16896u
#define GEMM_SMEM 85504u
__global__ __launch_bounds__(256) void k_gemm() {
    const int b = blockIdx.z, tap = blockIdx.x;
    const int pbase = blockIdx.y * 256;
    const int tid = threadIdx.x;
    const int warp = tid >> 5, lane = tid & 31;
    const int wm = warp >> 2, wn = warp & 3;
    const int g = lane >> 2, t = lane & 3;

    extern __shared__ __align__(16) unsigned char sm[];
    typedef __nv_bfloat16 bf;
    bf* AFH = (bf*)(sm + AFH_OFF);       // row stride 136
    bf* AFL = (bf*)(sm + AFL_OFF);

    float acc[2][8][4];
    #pragma unroll
    for (int i = 0; i < 2; i++)
        #pragma unroll
        for (int j = 0; j < 8; j++)
            #pragma unroll
            for (int k = 0; k < 4; k++) acc[i][j][k] = 0.f;

    const bf* wh = g_wh + ((size_t)(b * 576 + tap * 64)) * 128;
    const bf* wl = g_wl + ((size_t)(b * 576 + tap * 64)) * 128;
    const bf* xh = g_xh + (size_t)b * C_IN * P_IMG;
    const bf* xl = g_xl + (size_t)b * C_IN * P_IMG;

    const int a_row = lane & 15;
    const int a_col = (lane & 16) ? 8 : 0;
    const int b_row = lane & 15;
    const int b_off = (lane & 16) ? 8 : 0;

    #define FILL_B(kc, st) do {                                                \
        bf* bh_ = (bf*)(sm + BST_OFF + (st) * BST_SZ);                         \
        bf* bl_ = bh_ + 16 * 264;                                              \
        _Pragma("unroll")                                                      \
        for (int i_ = 0; i_ < 4; i_++) {                                       \
            int idx_ = i_ * 256 + tid;                                         \
            int hl_ = idx_ >> 9, j_ = idx_ & 511;                              \
            int r_ = j_ >> 5, c_ = j_ & 31;                                    \
            const bf* s_ = (hl_ ? xl : xh) + (size_t)((kc) + r_) * P_IMG       \
                           + pbase + c_ * 8;                                   \
            cp16((hl_ ? bl_ : bh_) + r_ * 264 + c_ * 8, s_);                   \
        }                                                                      \
    } while (0)

    // prologue: full A (8 cp16/thread) + B0 as group0, B1 as group1
    #pragma unroll
    for (int i_ = 0; i_ < 8; i_++) {
        int idx_ = i_ * 256 + tid;
        int hl_ = idx_ >> 10, j_ = idx_ & 1023;
        int r_ = j_ >> 4, c_ = j_ & 15;
        const bf* s_ = (hl_ ? wl : wh) + r_ * 128 + c_ * 8;
        cp16((hl_ ? AFL : AFH) + r_ * 136 + c_ * 8, s_);
    }
    FILL_B(0, 0);
    CP_COMMIT();
    FILL_B(16, 1);
    CP_COMMIT();

    #pragma unroll
    for (int it = 0; it < 8; it++) {
        const int s = it % 3;
        CP_WAIT1();
        __syncthreads();
        if (it < 6) FILL_B((it + 2) * 16, (it + 2) % 3);
        CP_COMMIT();

        const int kc = it * 16;
        uint32_t ah[2][4], al[2][4];
        #pragma unroll
        for (int mt = 0; mt < 2; mt++) {
            int row = wm * 32 + mt * 16 + a_row;
            ldsm_x4(ah[mt], AFH + row * 136 + kc + a_col);
            ldsm_x4(al[mt], AFL + row * 136 + kc + a_col);
        }
        bf* bh_ = (bf*)(sm + BST_OFF + s * BST_SZ);
        bf* bl_ = bh_ + 16 * 264;
        #pragma unroll
        for (int ntp = 0; ntp < 4; ntp++) {
            uint32_t bh[4], bl[4];
            int col = wn * 64 + ntp * 16 + b_off;
            ldsm_x4t(bh, bh_ + b_row * 264 + col);
            ldsm_x4t(bl, bl_ + b_row * 264 + col);
            #pragma unroll
            for (int mt = 0; mt < 2; mt++) {
                mma_bf16(acc[mt][2 * ntp],     ah[mt], bh[0], bh[1]);
                mma_bf16(acc[mt][2 * ntp],     ah[mt], bl[0], bl[1]);
                mma_bf16(acc[mt][2 * ntp],     al[mt], bh[0], bh[1]);
                mma_bf16(acc[mt][2 * ntp + 1], ah[mt], bh[2], bh[3]);
                mma_bf16(acc[mt][2 * ntp + 1], ah[mt], bl[2], bl[3]);
                mma_bf16(acc[mt][2 * ntp + 1], al[mt], bh[2], bh[3]);
            }
        }
    }
    #undef FILL_B
    __syncthreads();

    // epilogue: smem transpose -> fp16 128B-row stores in [p*9+tap][64] layout
    float (*S)[68] = (float(*)[68])sm;
    __half* vout = g_vals2h + (size_t)b * VB + (size_t)tap * 64;
    const int c8 = tid & 7;
    const float* vbp = &g_vbias[b * 576 + tap * 64];
    float vb[8];
    #pragma unroll
    for (int j = 0; j < 8; j++) vb[j] = vbp[c8 * 8 + j];
    #pragma unroll
    for (int pass = 0; pass < 4; pass++) {
        if (wn == pass) {
            #pragma unroll
            for (int mt = 0; mt < 2; mt++) {
                int o = wm * 32 + mt * 16 + g;
                #pragma unroll
                for (int nt = 0; nt < 8; nt++) {
                    int pl = nt * 8 + 2 * t;
                    S[pl][o]         = acc[mt][nt][0];
                    S[pl + 1][o]     = acc[mt][nt][1];
                    S[pl][o + 8]     = acc[mt][nt][2];
                    S[pl + 1][o + 8] = acc[mt][nt][3];
                }
            }
        }
        __syncthreads();
        #pragma unroll
        for (int i = 0; i < 2; i++) {
            int idx = tid + i * 256;
            int pl = idx >> 3;           // 0..63 (c8 invariant)
            float4 f0 = *(const float4*)&S[pl][c8 * 8];
            float4 f1 = *(const float4*)&S[pl][c8 * 8 + 4];
            __half2 h[4];
            h[0] = __floats2half2_rn(f0.x + vb[0], f0.y + vb[1]);
            h[1] = __floats2half2_rn(f0.z + vb[2], f0.w + vb[3]);
            h[2] = __floats2half2_rn(f1.x + vb[4], f1.y + vb[5]);
            h[3] = __floats2half2_rn(f1.z + vb[6], f1.w + vb[7]);
            *(uint4*)(vout + (size_t)(pbase + pass * 64 + pl) * 576 + c8 * 8) = *(uint4*)h;
        }
        __syncthreads();
    }
}

// ---------------- K4: build splat record table ----------------
__device__ __forceinline__ void emit_rec(int m, float wt, int yi, int xi) {
    if (yi < 0)          { yi = -yi;        xi = (xi + 512) & 1023; }
    else if (yi >= 512)  { yi = 1024 - yi;  xi = (xi + 512) & 1023; }
    if (yi > 511) yi = 511;
    if (yi < 0)   yi = 0;
    int idx = yi * 1024 + xi;
    int slot = atomicAdd(&g_cnt[idx], 1);
    if (slot < MAXREC) g_rec[(size_t)idx * MAXREC + slot] = make_int2(m, __float_as_int(wt));
}

__global__ __launch_bounds__(256) void k_build(const float* __restrict__ grid) {
    int m = blockIdx.x * 256 + threadIdx.x;
    if (m >= NPTS) return;
    float2 gxy = ((const float2*)grid)[m];
    float px = (gxy.x + 1.0f) * 0.5f * 1023.0f;
    float py = (gxy.y + 1.0f) * 0.5f * 511.0f;
    float fpx = floorf(px), fpy = floorf(py);
    int x0 = (int)fpx, y0 = (int)fpy;
    float fx = px - fpx, fy = py - fpy;
    float wx0 = 1.0f - fx, wy0 = 1.0f - fy;
    int x0w = x0 & 1023, x1w = (x0 + 1) & 1023;
    emit_rec(m, wx0 * wy0, y0,     x0w);
    emit_rec(m, wx0 * fy,  y0 + 1, x0w);
    emit_rec(m, fx  * wy0, y0,     x1w);
    emit_rec(m, fx  * fy,  y0 + 1, x1w);
}

// ---------------- K5: gather (both batches) + div + bias + GN2 stats ------
// Records for the warp's 4 pixels prefetched up-front; per-pixel record loop
// is depth-2 software-pipelined (loads for r+2 issue before FMAs consume r).
__global__ __launch_bounds__(256) void k_gather(float* __restrict__ out) {
    int base = blockIdx.x * 256;         // 256 pixels per block
    int tid = threadIdx.x;
    int w = tid >> 5, lane = tid & 31;
    __shared__ float buf[2][64][33];
    float sums[2][8], ssqs[2][8];
    #pragma unroll
    for (int b = 0; b < 2; b++)
        #pragma unroll
        for (int r = 0; r < 8; r++) { sums[b][r] = 0.f; ssqs[b][r] = 0.f; }

    const __half2* v0 = (const __half2*)g_vals2h;                 // batch 0
    const __half2* v1 = (const __half2*)(g_vals2h + (size_t)VB);  // batch 1
    float bz0 = g_bias2[2 * lane], bz1 = g_bias2[2 * lane + 1];

    for (int t = 0; t < 8; t++) {
        int pb = base + t * 32;
        // prefetch all 4 pixels' counts + records (independent coalesced loads)
        int cnt[4]; int2 rec[4];
        #pragma unroll
        for (int jj = 0; jj < 4; jj++) {
            int p = pb + jj * 8 + w;
            int c = g_cnt[p];
            if (c > MAXREC) c = MAXREC;
            cnt[jj] = c;
            rec[jj] = make_int2(0, 0);
            if (lane < c) rec[jj] = g_rec[(size_t)p * MAXREC + lane];
        }
        #pragma unroll
        for (int jj = 0; jj < 4; jj++) {
            int pp = jj * 8 + w;
            const int c = cnt[jj];
            float a0x = 0.f, a0y = 0.f, a1x = 0.f, a1y = 0.f, den = 0.f;
            // depth-2 pipelined record loop
            float2 f0a = make_float2(0.f, 0.f), f1a = f0a;
            float2 f0b = f0a, f1b = f0a;
            if (c > 0) {
                int rid = __shfl_sync(0xffffffffu, rec[jj].x, 0);
                f0a = __half22float2(v0[(size_t)rid * 32 + lane]);
                f1a = __half22float2(v1[(size_t)rid * 32 + lane]);
            }
            if (c > 1) {
                int rid = __shfl_sync(0xffffffffu, rec[jj].x, 1);
                f0b = __half22float2(v0[(size_t)rid * 32 + lane]);
                f1b = __half22float2(v1[(size_t)rid * 32 + lane]);
            }
            for (int r = 0; r < c; r++) {
                float2 c0 = f0a, c1 = f1a;
                f0a = f0b; f1a = f1b;
                if (r + 2 < c) {
                    int rid = __shfl_sync(0xffffffffu, rec[jj].x, r + 2);
                    f0b = __half22float2(v0[(size_t)rid * 32 + lane]);
                    f1b = __half22float2(v1[(size_t)rid * 32 + lane]);
                }
                float wt = __int_as_float(__shfl_sync(0xffffffffu, rec[jj].y, r));
                a0x += wt * c0.x; a0y += wt * c0.y;
                a1x += wt * c1.x; a1y += wt * c1.y;
                den += wt;
            }
            float rd = 1.0f / fmaxf(den, 1e-8f);
            buf[0][2 * lane][pp]     = a0x * rd + bz0;
            buf[0][2 * lane + 1][pp] = a0y * rd + bz1;
            buf[1][2 * lane][pp]     = a1x * rd + bz0;
            buf[1][2 * lane + 1][pp] = a1y * rd + bz1;
        }
        __syncthreads();
        #pragma unroll
        for (int b = 0; b < 2; b++) {
            #pragma unroll
            for (int r = 0; r < 8; r++) {
                int c = r * 8 + w;
                float v = buf[b][c][lane];
                out[((size_t)(b * 64 + c)) * HW + pb + lane] = v;
                sums[b][r] += v; ssqs[b][r] += v * v;
            }
        }
        __syncthreads();
    }
    #pragma unroll
    for (int b = 0; b < 2; b++) {
        #pragma unroll
        for (int r = 0; r < 8; r++) {
            float s = sums[b][r], q = ssqs[b][r];
            for (int off = 16; off; off >>= 1) {
                s += __shfl_down_sync(0xffffffffu, s, off);
                q += __shfl_down_sync(0xffffffffu, q, off);
            }
            if (lane == 0) {
                atomicAdd(&g_gn2sum[b * 64 + r * 8 + w], s);
                atomicAdd(&g_gn2ssq[b * 64 + r * 8 + w], q);
            }
        }
    }
}

// ---------------- K6: GN2 + exact GELU ----------------
__global__ __launch_bounds__(256) void k_final(float* __restrict__ out,
                                               const float* __restrict__ gamma2,
                                               const float* __restrict__ beta2) {
    size_t i4 = (size_t)blockIdx.x * 256 + threadIdx.x;   // float4 index
    int bc = (int)(i4 >> 17);            // 131072 float4 per (b,c) row
    int b = bc >> 6, c = bc & 63;
    int g = c >> 1;                      // 2 channels per group
    float S = g_gn2sum[b * 64 + 2 * g] + g_gn2sum[b * 64 + 2 * g + 1];
    float Q = g_gn2ssq[b * 64 + 2 * g] + g_gn2ssq[b * 64 + 2 * g + 1];
    float mu  = S * (1.0f / 1048576.0f);
    float var = Q * (1.0f / 1048576.0f) - mu * mu;
    float sc = rsqrtf(var + 1e-5f) * gamma2[c];
    float sh = beta2[c] - mu * sc;
    float4 v = ((float4*)out)[i4];
    float t;
    t = v.x * sc + sh; v.x = 0.5f * t * (1.0f + erff(t * 0.70710678f));
    t = v.y * sc + sh; v.y = 0.5f * t * (1.0f + erff(t * 0.70710678f));
    t = v.z * sc + sh; v.z = 0.5f * t * (1.0f + erff(t * 0.70710678f));
    t = v.w * sc + sh; v.w = 0.5f * t * (1.0f + erff(t * 0.70710678f));
    ((float4*)out)[i4] = v;
}

// ---------------- launch ----------------
extern "C" void kernel_launch(void* const* d_in, const int* in_sizes, int n_in,
                              void* d_out, int out_size) {
    const float* x          = (const float*)d_in[0];
    const float* grid       = (const float*)d_in[1];
    const float* gamma1     = (const float*)d_in[2];
    const float* beta1      = (const float*)d_in[3];
    const float* w_conv     = (const float*)d_in[4];
    const float* splat_bias = (const float*)d_in[5];
    const float* w_post     = (const float*)d_in[6];
    const float* b_post     = (const float*)d_in[7];
    const float* gamma2     = (const float*)d_in[8];
    const float* beta2      = (const float*)d_in[9];
    float* out = (float*)d_out;

    cudaFuncSetAttribute(k_gemm, cudaFuncAttributeMaxDynamicSharedMemorySize,
                         GEMM_SMEM);

    k_zero<<<2048, 256>>>();
    k_gn1split<<<dim3(256, 4), 256>>>(x);
    k_prep<<<576, 128>>>(w_conv, w_post, gamma1, beta1, splat_bias, b_post);
    k_gemm<<<dim3(9, 512, 2), 256, GEMM_SMEM>>>();
    k_build<<<4608, 256>>>(grid);
    k_gather<<<2048, 256>>>(out);
    k_final<<<65536, 256>>>(out, gamma2, beta2);
}

// round 16
// speedup vs baseline: 1.3926x; 1.3926x over previous
#include <cuda_runtime.h>
#include <cuda_bf16.h>
#include <cuda_fp16.h>
#include <cstdint>
#include <stdint.h>
#include <math.h>

// ---------------- problem constants ----------------
#define HP    256
#define WPIX  512
#define P_IMG 131072          // HP*WPIX  (low-res pixels)
#define NPTS  1179648         // P_IMG*9  (splat points)
#define H_OUT 512
#define W_OUT 1024
#define HW    524288          // H_OUT*W_OUT
#define C_IN  128
#define C_OUT 64
#define VB    75497472        // NPTS*64  (vals2 elements per batch)
#define MAXREC 24

// ---------------- device scratch (allocation-free) ----------------
__device__ __half g_vals2h[(size_t)2 * VB];        // [b][p*9+tap][64]  fp16
__device__ int2  g_rec[(size_t)HW * MAXREC];       // splat record table
__device__ int   g_cnt[HW];
__device__ __nv_bfloat16 g_wh[2 * 576 * 128];      // folded weights hi (row m = tap*64+o)
__device__ __nv_bfloat16 g_wl[2 * 576 * 128];      // folded weights lo
__device__ __nv_bfloat16 g_xh[(size_t)2 * C_IN * P_IMG];  // x split hi
__device__ __nv_bfloat16 g_xl[(size_t)2 * C_IN * P_IMG];  // x split lo
__device__ float g_vbias[2 * 576];
__device__ float g_bias2[64];
__device__ float g_gn1sum[64];                     // [b][32 groups]
__device__ float g_gn1ssq[64];
__device__ float g_gn2sum[128];                    // [b][64 ch]
__device__ float g_gn2ssq[128];

// ---------------- K0: zero counters/stats ----------------
__global__ void k_zero() {
    int i = blockIdx.x * 256 + threadIdx.x;
    if (i < HW) g_cnt[i] = 0;
    if (i < 64)  { g_gn1sum[i] = 0.f; g_gn1ssq[i] = 0.f; }
    if (i < 128) { g_gn2sum[i] = 0.f; g_gn2ssq[i] = 0.f; }
}

// ---------------- K1: GroupNorm-1 stats + bf16 hi/lo split (fused) --------
__global__ __launch_bounds__(256) void k_gn1split(const float* __restrict__ x) {
    int bc = blockIdx.x;                 // b*128 + c
    size_t rowoff = (size_t)bc * P_IMG + (size_t)blockIdx.y * 32768;
    const float4* p = (const float4*)(x + rowoff);
    __nv_bfloat162* ph = (__nv_bfloat162*)(g_xh + rowoff);
    __nv_bfloat162* pl = (__nv_bfloat162*)(g_xl + rowoff);
    float s = 0.f, q = 0.f;
    for (int i = threadIdx.x; i < 8192; i += 256) {
        float4 v = p[i];
        s += v.x + v.y + v.z + v.w;
        q += v.x * v.x + v.y * v.y + v.z * v.z + v.w * v.w;
        __nv_bfloat16 hx = __float2bfloat16(v.x);
        __nv_bfloat16 hy = __float2bfloat16(v.y);
        __nv_bfloat16 hz = __float2bfloat16(v.z);
        __nv_bfloat16 hw = __float2bfloat16(v.w);
        ph[2 * i]     = __halves2bfloat162(hx, hy);
        ph[2 * i + 1] = __halves2bfloat162(hz, hw);
        pl[2 * i]     = __halves2bfloat162(__float2bfloat16(v.x - __bfloat162float(hx)),
                                           __float2bfloat16(v.y - __bfloat162float(hy)));
        pl[2 * i + 1] = __halves2bfloat162(__float2bfloat16(v.z - __bfloat162float(hz)),
                                           __float2bfloat16(v.w - __bfloat162float(hw)));
    }
    __shared__ float sh1[8], sh2[8];
    for (int off = 16; off; off >>= 1) {
        s += __shfl_down_sync(0xffffffffu, s, off);
        q += __shfl_down_sync(0xffffffffu, q, off);
    }
    int lane = threadIdx.x & 31, warp = threadIdx.x >> 5;
    if (lane == 0) { sh1[warp] = s; sh2[warp] = q; }
    __syncthreads();
    if (threadIdx.x == 0) {
        float S = 0.f, Q = 0.f;
        for (int i = 0; i < 8; i++) { S += sh1[i]; Q += sh2[i]; }
        int b = bc >> 7, g = (bc & 127) >> 2;     // 4 channels per group
        atomicAdd(&g_gn1sum[b * 32 + g], S);
        atomicAdd(&g_gn1ssq[b * 32 + g], Q);
    }
}

// ---------------- K2: fold w_post . w_conv . GN1 into wh/wl/vbias/bias2 ----
__global__ __launch_bounds__(128) void k_prep(const float* __restrict__ w_conv,
                                              const float* __restrict__ w_post,
                                              const float* __restrict__ gamma1,
                                              const float* __restrict__ beta1,
                                              const float* __restrict__ splat_bias,
                                              const float* __restrict__ b_post) {
    int m = blockIdx.x;                  // tap-major row: m = tap*64 + o
    int tap = m >> 6, o = m & 63;
    int c = threadIdx.x;                 // 0..127
    __shared__ float sp[64];
    __shared__ float red[128];
    if (c < 64) sp[c] = w_post[o * 64 + c];
    __syncthreads();
    float w2 = 0.f;
    #pragma unroll 8
    for (int k = 0; k < 64; k++) w2 += sp[k] * w_conv[(k * 9 + tap) * 128 + c];

    float ga = gamma1[c], be = beta1[c];
    int g = c >> 2;
    for (int b = 0; b < 2; b++) {
        float su = g_gn1sum[b * 32 + g], sq = g_gn1ssq[b * 32 + g];
        float mu  = su * (1.0f / 524288.0f);
        float var = sq * (1.0f / 524288.0f) - mu * mu;
        float rs  = rsqrtf(var + 1e-5f);
        float sc  = rs * ga;
        float sh  = be - mu * sc;
        float wsv = w2 * sc;
        __nv_bfloat16 h = __float2bfloat16(wsv);
        g_wh[((size_t)b * 576 + m) * 128 + c] = h;
        g_wl[((size_t)b * 576 + m) * 128 + c] =
            __float2bfloat16(wsv - __bfloat162float(h));
        red[c] = w2 * sh;
        __syncthreads();
        for (int s = 64; s > 0; s >>= 1) { if (c < s) red[c] += red[c + s]; __syncthreads(); }
        if (c == 0) g_vbias[b * 576 + m] = red[0];
        __syncthreads();
    }
    if (tap == 0) {
        red[c] = (c < 64) ? sp[c] * splat_bias[c] : 0.f;
        __syncthreads();
        for (int s = 64; s > 0; s >>= 1) { if (c < s) red[c] += red[c + s]; __syncthreads(); }
        if (c == 0) g_bias2[o] = red[0] + b_post[o];
    }
}

// ---------------- tensor-core / async helpers ----------------
__device__ __forceinline__ void ldsm_x4(uint32_t* r, const void* p) {
    uint32_t a = (uint32_t)__cvta_generic_to_shared(p);
    asm volatile("ldmatrix.sync.aligned.m8n8.x4.shared.b16 {%0,%1,%2,%3}, [%4];"
        : "=r"(r[0]), "=r"(r[1]), "=r"(r[2]), "=r"(r[3]) : "r"(a));
}
__device__ __forceinline__ void ldsm_x4t(uint32_t* r, const void* p) {
    uint32_t a = (uint32_t)__cvta_generic_to_shared(p);
    asm volatile("ldmatrix.sync.aligned.m8n8.x4.trans.shared.b16 {%0,%1,%2,%3}, [%4];"
        : "=r"(r[0]), "=r"(r[1]), "=r"(r[2]), "=r"(r[3]) : "r"(a));
}
__device__ __forceinline__ void mma_bf16(float* c, const uint32_t* a,
                                         uint32_t b0, uint32_t b1) {
    asm volatile("mma.sync.aligned.m16n8k16.row.col.f32.bf16.bf16.f32 "
        "{%0,%1,%2,%3}, {%4,%5,%6,%7}, {%8,%9}, {%0,%1,%2,%3};"
        : "+f"(c[0]), "+f"(c[1]), "+f"(c[2]), "+f"(c[3])
        : "r"(a[0]), "r"(a[1]), "r"(a[2]), "r"(a[3]), "r"(b0), "r"(b1));
}
__device__ __forceinline__ void cp16(void* dst, const void* src) {
    uint32_t d = (uint32_t)__cvta_generic_to_shared(dst);
    asm volatile("cp.async.cg.shared.global [%0], [%1], 16;" :: "r"(d), "l"(src));
}
#define CP_COMMIT() asm volatile("cp.async.commit_group;")
#define CP_WAIT1()  asm volatile("cp.async.wait_group 1;")

// ---------------- K3: pipelined tensor-core GEMM (split bf16, 3-term) ------
// A (64x128 hi+lo) resident in smem for the whole K; 3-stage B ring;
// ONE barrier + one wait_group per k-chunk.   (unchanged from R13 best)
#define AFH_OFF 0u
#define AFL_OFF 17408u
#define BST_OFF 34816u
#define BST_SZ  16896u
#define GEMM_SMEM 85504u
__global__ __launch_bounds__(256) void k_gemm() {
    const int b = blockIdx.z, tap = blockIdx.x;
    const int pbase = blockIdx.y * 256;
    const int tid = threadIdx.x;
    const int warp = tid >> 5, lane = tid & 31;
    const int wm = warp >> 2, wn = warp & 3;
    const int g = lane >> 2, t = lane & 3;

    extern __shared__ __align__(16) unsigned char sm[];
    typedef __nv_bfloat16 bf;
    bf* AFH = (bf*)(sm + AFH_OFF);       // row stride 136
    bf* AFL = (bf*)(sm + AFL_OFF);

    float acc[2][8][4];
    #pragma unroll
    for (int i = 0; i < 2; i++)
        #pragma unroll
        for (int j = 0; j < 8; j++)
            #pragma unroll
            for (int k = 0; k < 4; k++) acc[i][j][k] = 0.f;

    const bf* wh = g_wh + ((size_t)(b * 576 + tap * 64)) * 128;
    const bf* wl = g_wl + ((size_t)(b * 576 + tap * 64)) * 128;
    const bf* xh = g_xh + (size_t)b * C_IN * P_IMG;
    const bf* xl = g_xl + (size_t)b * C_IN * P_IMG;

    const int a_row = lane & 15;
    const int a_col = (lane & 16) ? 8 : 0;
    const int b_row = lane & 15;
    const int b_off = (lane & 16) ? 8 : 0;

    #define FILL_B(kc, st) do {                                                \
        bf* bh_ = (bf*)(sm + BST_OFF + (st) * BST_SZ);                         \
        bf* bl_ = bh_ + 16 * 264;                                              \
        _Pragma("unroll")                                                      \
        for (int i_ = 0; i_ < 4; i_++) {                                       \
            int idx_ = i_ * 256 + tid;                                         \
            int hl_ = idx_ >> 9, j_ = idx_ & 511;                              \
            int r_ = j_ >> 5, c_ = j_ & 31;                                    \
            const bf* s_ = (hl_ ? xl : xh) + (size_t)((kc) + r_) * P_IMG       \
                           + pbase + c_ * 8;                                   \
            cp16((hl_ ? bl_ : bh_) + r_ * 264 + c_ * 8, s_);                   \
        }                                                                      \
    } while (0)

    // prologue: full A (8 cp16/thread) + B0 as group0, B1 as group1
    #pragma unroll
    for (int i_ = 0; i_ < 8; i_++) {
        int idx_ = i_ * 256 + tid;
        int hl_ = idx_ >> 10, j_ = idx_ & 1023;
        int r_ = j_ >> 4, c_ = j_ & 15;
        const bf* s_ = (hl_ ? wl : wh) + r_ * 128 + c_ * 8;
        cp16((hl_ ? AFL : AFH) + r_ * 136 + c_ * 8, s_);
    }
    FILL_B(0, 0);
    CP_COMMIT();
    FILL_B(16, 1);
    CP_COMMIT();

    #pragma unroll
    for (int it = 0; it < 8; it++) {
        const int s = it % 3;
        CP_WAIT1();
        __syncthreads();
        if (it < 6) FILL_B((it + 2) * 16, (it + 2) % 3);
        CP_COMMIT();

        const int kc = it * 16;
        uint32_t ah[2][4], al[2][4];
        #pragma unroll
        for (int mt = 0; mt < 2; mt++) {
            int row = wm * 32 + mt * 16 + a_row;
            ldsm_x4(ah[mt], AFH + row * 136 + kc + a_col);
            ldsm_x4(al[mt], AFL + row * 136 + kc + a_col);
        }
        bf* bh_ = (bf*)(sm + BST_OFF + s * BST_SZ);
        bf* bl_ = bh_ + 16 * 264;
        #pragma unroll
        for (int ntp = 0; ntp < 4; ntp++) {
            uint32_t bh[4], bl[4];
            int col = wn * 64 + ntp * 16 + b_off;
            ldsm_x4t(bh, bh_ + b_row * 264 + col);
            ldsm_x4t(bl, bl_ + b_row * 264 + col);
            #pragma unroll
            for (int mt = 0; mt < 2; mt++) {
                mma_bf16(acc[mt][2 * ntp],     ah[mt], bh[0], bh[1]);
                mma_bf16(acc[mt][2 * ntp],     ah[mt], bl[0], bl[1]);
                mma_bf16(acc[mt][2 * ntp],     al[mt], bh[0], bh[1]);
                mma_bf16(acc[mt][2 * ntp + 1], ah[mt], bh[2], bh[3]);
                mma_bf16(acc[mt][2 * ntp + 1], ah[mt], bl[2], bl[3]);
                mma_bf16(acc[mt][2 * ntp + 1], al[mt], bh[2], bh[3]);
            }
        }
    }
    #undef FILL_B
    __syncthreads();

    // epilogue: smem transpose -> fp16 128B-row stores in [p*9+tap][64] layout
    float (*S)[68] = (float(*)[68])sm;
    __half* vout = g_vals2h + (size_t)b * VB + (size_t)tap * 64;
    const int c8 = tid & 7;
    const float* vbp = &g_vbias[b * 576 + tap * 64];
    float vb[8];
    #pragma unroll
    for (int j = 0; j < 8; j++) vb[j] = vbp[c8 * 8 + j];
    #pragma unroll
    for (int pass = 0; pass < 4; pass++) {
        if (wn == pass) {
            #pragma unroll
            for (int mt = 0; mt < 2; mt++) {
                int o = wm * 32 + mt * 16 + g;
                #pragma unroll
                for (int nt = 0; nt < 8; nt++) {
                    int pl = nt * 8 + 2 * t;
                    S[pl][o]         = acc[mt][nt][0];
                    S[pl + 1][o]     = acc[mt][nt][1];
                    S[pl][o + 8]     = acc[mt][nt][2];
                    S[pl + 1][o + 8] = acc[mt][nt][3];
                }
            }
        }
        __syncthreads();
        #pragma unroll
        for (int i = 0; i < 2; i++) {
            int idx = tid + i * 256;
            int pl = idx >> 3;           // 0..63 (c8 invariant)
            float4 f0 = *(const float4*)&S[pl][c8 * 8];
            float4 f1 = *(const float4*)&S[pl][c8 * 8 + 4];
            __half2 h[4];
            h[0] = __floats2half2_rn(f0.x + vb[0], f0.y + vb[1]);
            h[1] = __floats2half2_rn(f0.z + vb[2], f0.w + vb[3]);
            h[2] = __floats2half2_rn(f1.x + vb[4], f1.y + vb[5]);
            h[3] = __floats2half2_rn(f1.z + vb[6], f1.w + vb[7]);
            *(uint4*)(vout + (size_t)(pbase + pass * 64 + pl) * 576 + c8 * 8) = *(uint4*)h;
        }
        __syncthreads();
    }
}

// ---------------- K4: build splat record table ----------------
__device__ __forceinline__ void emit_rec(int m, float wt, int yi, int xi) {
    if (yi < 0)          { yi = -yi;        xi = (xi + 512) & 1023; }
    else if (yi >= 512)  { yi = 1024 - yi;  xi = (xi + 512) & 1023; }
    if (yi > 511) yi = 511;
    if (yi < 0)   yi = 0;
    int idx = yi * 1024 + xi;
    int slot = atomicAdd(&g_cnt[idx], 1);
    if (slot < MAXREC) g_rec[(size_t)idx * MAXREC + slot] = make_int2(m, __float_as_int(wt));
}

__global__ __launch_bounds__(256) void k_build(const float* __restrict__ grid) {
    int m = blockIdx.x * 256 + threadIdx.x;
    if (m >= NPTS) return;
    float2 gxy = ((const float2*)grid)[m];
    float px = (gxy.x + 1.0f) * 0.5f * 1023.0f;
    float py = (gxy.y + 1.0f) * 0.5f * 511.0f;
    float fpx = floorf(px), fpy = floorf(py);
    int x0 = (int)fpx, y0 = (int)fpy;
    float fx = px - fpx, fy = py - fpy;
    float wx0 = 1.0f - fx, wy0 = 1.0f - fy;
    int x0w = x0 & 1023, x1w = (x0 + 1) & 1023;
    emit_rec(m, wx0 * wy0, y0,     x0w);
    emit_rec(m, wx0 * fy,  y0 + 1, x0w);
    emit_rec(m, fx  * wy0, y0,     x1w);
    emit_rec(m, fx  * fy,  y0 + 1, x1w);
}

// ---------------- K5: gather (both batches) + div + bias  (NO stats) ------
__global__ __launch_bounds__(256) void k_gather(float* __restrict__ out) {
    int base = blockIdx.x * 256;         // 256 pixels per block
    int tid = threadIdx.x;
    int w = tid >> 5, lane = tid & 31;
    __shared__ float buf[2][64][33];

    const __half2* v0 = (const __half2*)g_vals2h;                 // batch 0
    const __half2* v1 = (const __half2*)(g_vals2h + (size_t)VB);  // batch 1
    float bz0 = g_bias2[2 * lane], bz1 = g_bias2[2 * lane + 1];

    for (int t = 0; t < 8; t++) {
        int pb = base + t * 32;
        for (int jj = 0; jj < 4; jj++) {
            int pp = jj * 8 + w;
            int p = pb + pp;
            int cnt = g_cnt[p];
            if (cnt > MAXREC) cnt = MAXREC;
            const int2* rp = &g_rec[(size_t)p * MAXREC];
            int2 myrec = make_int2(0, 0);
            if (lane < cnt) myrec = rp[lane];
            float a0x = 0.f, a0y = 0.f, a1x = 0.f, a1y = 0.f, den = 0.f;
            for (int r = 0; r < cnt; r++) {
                int rid  = __shfl_sync(0xffffffffu, myrec.x, r);
                float wt = __int_as_float(__shfl_sync(0xffffffffu, myrec.y, r));
                float2 f0 = __half22float2(v0[(size_t)rid * 32 + lane]);
                float2 f1 = __half22float2(v1[(size_t)rid * 32 + lane]);
                a0x += wt * f0.x; a0y += wt * f0.y;
                a1x += wt * f1.x; a1y += wt * f1.y;
                den += wt;
            }
            float rd = 1.0f / fmaxf(den, 1e-8f);
            buf[0][2 * lane][pp]     = a0x * rd + bz0;
            buf[0][2 * lane + 1][pp] = a0y * rd + bz1;
            buf[1][2 * lane][pp]     = a1x * rd + bz0;
            buf[1][2 * lane + 1][pp] = a1y * rd + bz1;
        }
        __syncthreads();
        #pragma unroll
        for (int b = 0; b < 2; b++) {
            #pragma unroll
            for (int r = 0; r < 8; r++) {
                int c = r * 8 + w;
                out[((size_t)(b * 64 + c)) * HW + pb + lane] = buf[b][c][lane];
            }
        }
        __syncthreads();
    }
}

// ---------------- K5b: GN2 stats over out ----------------
__global__ __launch_bounds__(256) void k_stats(const float* __restrict__ out) {
    int bc = blockIdx.x;                 // b*64 + c
    const float4* p = (const float4*)(out + (size_t)bc * HW) + (size_t)blockIdx.y * 32768;
    float s = 0.f, q = 0.f;
    for (int i = threadIdx.x; i < 32768; i += 256) {
        float4 v = p[i];
        s += v.x + v.y + v.z + v.w;
        q += v.x * v.x + v.y * v.y + v.z * v.z + v.w * v.w;
    }
    __shared__ float sh1[8], sh2[8];
    for (int off = 16; off; off >>= 1) {
        s += __shfl_down_sync(0xffffffffu, s, off);
        q += __shfl_down_sync(0xffffffffu, q, off);
    }
    int lane = threadIdx.x & 31, warp = threadIdx.x >> 5;
    if (lane == 0) { sh1[warp] = s; sh2[warp] = q; }
    __syncthreads();
    if (threadIdx.x == 0) {
        float S = 0.f, Q = 0.f;
        for (int i = 0; i < 8; i++) { S += sh1[i]; Q += sh2[i]; }
        atomicAdd(&g_gn2sum[bc], S);
        atomicAdd(&g_gn2ssq[bc], Q);
    }
}

// ---------------- K6: GN2 + exact GELU ----------------
__global__ __launch_bounds__(256) void k_final(float* __restrict__ out,
                                               const float* __restrict__ gamma2,
                                               const float* __restrict__ beta2) {
    size_t i4 = (size_t)blockIdx.x * 256 + threadIdx.x;   // float4 index
    int bc = (int)(i4 >> 17);            // 131072 float4 per (b,c) row
    int b = bc >> 6, c = bc & 63;
    int g = c >> 1;                      // 2 channels per group
    float S = g_gn2sum[b * 64 + 2 * g] + g_gn2sum[b * 64 + 2 * g + 1];
    float Q = g_gn2ssq[b * 64 + 2 * g] + g_gn2ssq[b * 64 + 2 * g + 1];
    float mu  = S * (1.0f / 1048576.0f);
    float var = Q * (1.0f / 1048576.0f) - mu * mu;
    float sc = rsqrtf(var + 1e-5f) * gamma2[c];
    float sh = beta2[c] - mu * sc;
    float4 v = ((float4*)out)[i4];
    float t;
    t = v.x * sc + sh; v.x = 0.5f * t * (1.0f + erff(t * 0.70710678f));
    t = v.y * sc + sh; v.y = 0.5f * t * (1.0f + erff(t * 0.70710678f));
    t = v.z * sc + sh; v.z = 0.5f * t * (1.0f + erff(t * 0.70710678f));
    t = v.w * sc + sh; v.w = 0.5f * t * (1.0f + erff(t * 0.70710678f));
    ((float4*)out)[i4] = v;
}

// ---------------- launch ----------------
extern "C" void kernel_launch(void* const* d_in, const int* in_sizes, int n_in,
                              void* d_out, int out_size) {
    const float* x          = (const float*)d_in[0];
    const float* grid       = (const float*)d_in[1];
    const float* gamma1     = (const float*)d_in[2];
    const float* beta1      = (const float*)d_in[3];
    const float* w_conv     = (const float*)d_in[4];
    const float* splat_bias = (const float*)d_in[5];
    const float* w_post     = (const float*)d_in[6];
    const float* b_post     = (const float*)d_in[7];
    const float* gamma2     = (const float*)d_in[8];
    const float* beta2      = (const float*)d_in[9];
    float* out = (float*)d_out;

    cudaFuncSetAttribute(k_gemm, cudaFuncAttributeMaxDynamicSharedMemorySize,
                         GEMM_SMEM);

    k_zero<<<2048, 256>>>();
    k_gn1split<<<dim3(256, 4), 256>>>(x);
    k_prep<<<576, 128>>>(w_conv, w_post, gamma1, beta1, splat_bias, b_post);
    k_gemm<<<dim3(9, 512, 2), 256, GEMM_SMEM>>>();
    k_build<<<4608, 256>>>(grid);
    k_gather<<<2048, 256>>>(out);
    k_stats<<<dim3(128, 4), 256>>>(out);
    k_final<<<65536, 256>>>(out, gamma2, beta2);
}

// round 17
// speedup vs baseline: 1.4710x; 1.0563x over previous
#include <cuda_runtime.h>
#include <cuda_bf16.h>
#include <cuda_fp16.h>
#include <cstdint>
#include <stdint.h>
#include <math.h>

// ---------------- problem constants ----------------
#define HP    256
#define WPIX  512
#define P_IMG 131072          // HP*WPIX  (low-res pixels)
#define NPTS  1179648         // P_IMG*9  (splat points)
#define H_OUT 512
#define W_OUT 1024
#define HW    524288          // H_OUT*W_OUT
#define C_IN  128
#define C_OUT 64
#define VB    75497472        // NPTS*64  (vals2 elements per batch)
#define MAXREC 24

// ---------------- device scratch (allocation-free) ----------------
__device__ __half g_vals2h[(size_t)2 * VB];        // [b][p*9+tap][64]  fp16
__device__ int2  g_rec[(size_t)HW * MAXREC];       // splat record table
__device__ int   g_cnt[HW];
__device__ __nv_bfloat16 g_wh[2 * 576 * 128];      // folded weights hi (row m = tap*64+o)
__device__ __nv_bfloat16 g_wl[2 * 576 * 128];      // folded weights lo
__device__ __nv_bfloat16 g_xh[(size_t)2 * C_IN * P_IMG];  // x split hi
__device__ __nv_bfloat16 g_xl[(size_t)2 * C_IN * P_IMG];  // x split lo
__device__ float g_vbias[2 * 576];
__device__ float g_bias2[64];
__device__ float g_gn1sum[64];                     // [b][32 groups]
__device__ float g_gn1ssq[64];
__device__ float g_gn2sum[128];                    // [b][64 ch]
__device__ float g_gn2ssq[128];

// ---------------- K0: zero counters/stats ----------------
__global__ void k_zero() {
    int i = blockIdx.x * 256 + threadIdx.x;
    if (i < HW) g_cnt[i] = 0;
    if (i < 64)  { g_gn1sum[i] = 0.f; g_gn1ssq[i] = 0.f; }
    if (i < 128) { g_gn2sum[i] = 0.f; g_gn2ssq[i] = 0.f; }
}

// ---------------- K1: GroupNorm-1 stats + bf16 hi/lo split (fused) --------
__global__ __launch_bounds__(256) void k_gn1split(const float* __restrict__ x) {
    int bc = blockIdx.x;                 // b*128 + c
    size_t rowoff = (size_t)bc * P_IMG + (size_t)blockIdx.y * 32768;
    const float4* p = (const float4*)(x + rowoff);
    __nv_bfloat162* ph = (__nv_bfloat162*)(g_xh + rowoff);
    __nv_bfloat162* pl = (__nv_bfloat162*)(g_xl + rowoff);
    float s = 0.f, q = 0.f;
    for (int i = threadIdx.x; i < 8192; i += 256) {
        float4 v = p[i];
        s += v.x + v.y + v.z + v.w;
        q += v.x * v.x + v.y * v.y + v.z * v.z + v.w * v.w;
        __nv_bfloat16 hx = __float2bfloat16(v.x);
        __nv_bfloat16 hy = __float2bfloat16(v.y);
        __nv_bfloat16 hz = __float2bfloat16(v.z);
        __nv_bfloat16 hw = __float2bfloat16(v.w);
        ph[2 * i]     = __halves2bfloat162(hx, hy);
        ph[2 * i + 1] = __halves2bfloat162(hz, hw);
        pl[2 * i]     = __halves2bfloat162(__float2bfloat16(v.x - __bfloat162float(hx)),
                                           __float2bfloat16(v.y - __bfloat162float(hy)));
        pl[2 * i + 1] = __halves2bfloat162(__float2bfloat16(v.z - __bfloat162float(hz)),
                                           __float2bfloat16(v.w - __bfloat162float(hw)));
    }
    __shared__ float sh1[8], sh2[8];
    for (int off = 16; off; off >>= 1) {
        s += __shfl_down_sync(0xffffffffu, s, off);
        q += __shfl_down_sync(0xffffffffu, q, off);
    }
    int lane = threadIdx.x & 31, warp = threadIdx.x >> 5;
    if (lane == 0) { sh1[warp] = s; sh2[warp] = q; }
    __syncthreads();
    if (threadIdx.x == 0) {
        float S = 0.f, Q = 0.f;
        for (int i = 0; i < 8; i++) { S += sh1[i]; Q += sh2[i]; }
        int b = bc >> 7, g = (bc & 127) >> 2;     // 4 channels per group
        atomicAdd(&g_gn1sum[b * 32 + g], S);
        atomicAdd(&g_gn1ssq[b * 32 + g], Q);
    }
}

// ---------------- K2: fold w_post . w_conv . GN1 into wh/wl/vbias/bias2 ----
__global__ __launch_bounds__(128) void k_prep(const float* __restrict__ w_conv,
                                              const float* __restrict__ w_post,
                                              const float* __restrict__ gamma1,
                                              const float* __restrict__ beta1,
                                              const float* __restrict__ splat_bias,
                                              const float* __restrict__ b_post) {
    int m = blockIdx.x;                  // tap-major row: m = tap*64 + o
    int tap = m >> 6, o = m & 63;
    int c = threadIdx.x;                 // 0..127
    __shared__ float sp[64];
    __shared__ float red[128];
    if (c < 64) sp[c] = w_post[o * 64 + c];
    __syncthreads();
    float w2 = 0.f;
    #pragma unroll 8
    for (int k = 0; k < 64; k++) w2 += sp[k] * w_conv[(k * 9 + tap) * 128 + c];

    float ga = gamma1[c], be = beta1[c];
    int g = c >> 2;
    for (int b = 0; b < 2; b++) {
        float su = g_gn1sum[b * 32 + g], sq = g_gn1ssq[b * 32 + g];
        float mu  = su * (1.0f / 524288.0f);
        float var = sq * (1.0f / 524288.0f) - mu * mu;
        float rs  = rsqrtf(var + 1e-5f);
        float sc  = rs * ga;
        float sh  = be - mu * sc;
        float wsv = w2 * sc;
        __nv_bfloat16 h = __float2bfloat16(wsv);
        g_wh[((size_t)b * 576 + m) * 128 + c] = h;
        g_wl[((size_t)b * 576 + m) * 128 + c] =
            __float2bfloat16(wsv - __bfloat162float(h));
        red[c] = w2 * sh;
        __syncthreads();
        for (int s = 64; s > 0; s >>= 1) { if (c < s) red[c] += red[c + s]; __syncthreads(); }
        if (c == 0) g_vbias[b * 576 + m] = red[0];
        __syncthreads();
    }
    if (tap == 0) {
        red[c] = (c < 64) ? sp[c] * splat_bias[c] : 0.f;
        __syncthreads();
        for (int s = 64; s > 0; s >>= 1) { if (c < s) red[c] += red[c + s]; __syncthreads(); }
        if (c == 0) g_bias2[o] = red[0] + b_post[o];
    }
}

// ---------------- tensor-core / async helpers ----------------
__device__ __forceinline__ void ldsm_x4(uint32_t* r, const void* p) {
    uint32_t a = (uint32_t)__cvta_generic_to_shared(p);
    asm volatile("ldmatrix.sync.aligned.m8n8.x4.shared.b16 {%0,%1,%2,%3}, [%4];"
        : "=r"(r[0]), "=r"(r[1]), "=r"(r[2]), "=r"(r[3]) : "r"(a));
}
__device__ __forceinline__ void ldsm_x4t(uint32_t* r, const void* p) {
    uint32_t a = (uint32_t)__cvta_generic_to_shared(p);
    asm volatile("ldmatrix.sync.aligned.m8n8.x4.trans.shared.b16 {%0,%1,%2,%3}, [%4];"
        : "=r"(r[0]), "=r"(r[1]), "=r"(r[2]), "=r"(r[3]) : "r"(a));
}
__device__ __forceinline__ void mma_bf16(float* c, const uint32_t* a,
                                         uint32_t b0, uint32_t b1) {
    asm volatile("mma.sync.aligned.m16n8k16.row.col.f32.bf16.bf16.f32 "
        "{%0,%1,%2,%3}, {%4,%5,%6,%7}, {%8,%9}, {%0,%1,%2,%3};"
        : "+f"(c[0]), "+f"(c[1]), "+f"(c[2]), "+f"(c[3])
        : "r"(a[0]), "r"(a[1]), "r"(a[2]), "r"(a[3]), "r"(b0), "r"(b1));
}
__device__ __forceinline__ void cp16(void* dst, const void* src) {
    uint32_t d = (uint32_t)__cvta_generic_to_shared(dst);
    asm volatile("cp.async.cg.shared.global [%0], [%1], 16;" :: "r"(d), "l"(src));
}
#define CP_COMMIT() asm volatile("cp.async.commit_group;")
#define CP_WAIT1()  asm volatile("cp.async.wait_group 1;")

// ---------------- K3: pipelined tensor-core GEMM (split bf16, 3-term) ------
// A (64x128 hi+lo) resident in smem for the whole K; 3-stage B ring;
// ONE barrier + one wait_group per k-chunk.   (unchanged from R13 best)
#define AFH_OFF 0u
#define AFL_OFF 17408u
#define BST_OFF 34816u
#define BST_SZ  16896u
#define GEMM_SMEM 85504u
__global__ __launch_bounds__(256) void k_gemm() {
    const int b = blockIdx.z, tap = blockIdx.x;
    const int pbase = blockIdx.y * 256;
    const int tid = threadIdx.x;
    const int warp = tid >> 5, lane = tid & 31;
    const int wm = warp >> 2, wn = warp & 3;
    const int g = lane >> 2, t = lane & 3;

    extern __shared__ __align__(16) unsigned char sm[];
    typedef __nv_bfloat16 bf;
    bf* AFH = (bf*)(sm + AFH_OFF);       // row stride 136
    bf* AFL = (bf*)(sm + AFL_OFF);

    float acc[2][8][4];
    #pragma unroll
    for (int i = 0; i < 2; i++)
        #pragma unroll
        for (int j = 0; j < 8; j++)
            #pragma unroll
            for (int k = 0; k < 4; k++) acc[i][j][k] = 0.f;

    const bf* wh = g_wh + ((size_t)(b * 576 + tap * 64)) * 128;
    const bf* wl = g_wl + ((size_t)(b * 576 + tap * 64)) * 128;
    const bf* xh = g_xh + (size_t)b * C_IN * P_IMG;
    const bf* xl = g_xl + (size_t)b * C_IN * P_IMG;

    const int a_row = lane & 15;
    const int a_col = (lane & 16) ? 8 : 0;
    const int b_row = lane & 15;
    const int b_off = (lane & 16) ? 8 : 0;

    #define FILL_B(kc, st) do {                                                \
        bf* bh_ = (bf*)(sm + BST_OFF + (st) * BST_SZ);                         \
        bf* bl_ = bh_ + 16 * 264;                                              \
        _Pragma("unroll")                                                      \
        for (int i_ = 0; i_ < 4; i_++) {                                       \
            int idx_ = i_ * 256 + tid;                                         \
            int hl_ = idx_ >> 9, j_ = idx_ & 511;                              \
            int r_ = j_ >> 5, c_ = j_ & 31;                                    \
            const bf* s_ = (hl_ ? xl : xh) + (size_t)((kc) + r_) * P_IMG       \
                           + pbase + c_ * 8;                                   \
            cp16((hl_ ? bl_ : bh_) + r_ * 264 + c_ * 8, s_);                   \
        }                                                                      \
    } while (0)

    // prologue: full A (8 cp16/thread) + B0 as group0, B1 as group1
    #pragma unroll
    for (int i_ = 0; i_ < 8; i_++) {
        int idx_ = i_ * 256 + tid;
        int hl_ = idx_ >> 10, j_ = idx_ & 1023;
        int r_ = j_ >> 4, c_ = j_ & 15;
        const bf* s_ = (hl_ ? wl : wh) + r_ * 128 + c_ * 8;
        cp16((hl_ ? AFL : AFH) + r_ * 136 + c_ * 8, s_);
    }
    FILL_B(0, 0);
    CP_COMMIT();
    FILL_B(16, 1);
    CP_COMMIT();

    #pragma unroll
    for (int it = 0; it < 8; it++) {
        const int s = it % 3;
        CP_WAIT1();
        __syncthreads();
        if (it < 6) FILL_B((it + 2) * 16, (it + 2) % 3);
        CP_COMMIT();

        const int kc = it * 16;
        uint32_t ah[2][4], al[2][4];
        #pragma unroll
        for (int mt = 0; mt < 2; mt++) {
            int row = wm * 32 + mt * 16 + a_row;
            ldsm_x4(ah[mt], AFH + row * 136 + kc + a_col);
            ldsm_x4(al[mt], AFL + row * 136 + kc + a_col);
        }
        bf* bh_ = (bf*)(sm + BST_OFF + s * BST_SZ);
        bf* bl_ = bh_ + 16 * 264;
        #pragma unroll
        for (int ntp = 0; ntp < 4; ntp++) {
            uint32_t bh[4], bl[4];
            int col = wn * 64 + ntp * 16 + b_off;
            ldsm_x4t(bh, bh_ + b_row * 264 + col);
            ldsm_x4t(bl, bl_ + b_row * 264 + col);
            #pragma unroll
            for (int mt = 0; mt < 2; mt++) {
                mma_bf16(acc[mt][2 * ntp],     ah[mt], bh[0], bh[1]);
                mma_bf16(acc[mt][2 * ntp],     ah[mt], bl[0], bl[1]);
                mma_bf16(acc[mt][2 * ntp],     al[mt], bh[0], bh[1]);
                mma_bf16(acc[mt][2 * ntp + 1], ah[mt], bh[2], bh[3]);
                mma_bf16(acc[mt][2 * ntp + 1], ah[mt], bl[2], bl[3]);
                mma_bf16(acc[mt][2 * ntp + 1], al[mt], bh[2], bh[3]);
            }
        }
    }
    #undef FILL_B
    __syncthreads();

    // epilogue: smem transpose -> fp16 128B-row stores in [p*9+tap][64] layout
    float (*S)[68] = (float(*)[68])sm;
    __half* vout = g_vals2h + (size_t)b * VB + (size_t)tap * 64;
    const int c8 = tid & 7;
    const float* vbp = &g_vbias[b * 576 + tap * 64];
    float vb[8];
    #pragma unroll
    for (int j = 0; j < 8; j++) vb[j] = vbp[c8 * 8 + j];
    #pragma unroll
    for (int pass = 0; pass < 4; pass++) {
        if (wn == pass) {
            #pragma unroll
            for (int mt = 0; mt < 2; mt++) {
                int o = wm * 32 + mt * 16 + g;
                #pragma unroll
                for (int nt = 0; nt < 8; nt++) {
                    int pl = nt * 8 + 2 * t;
                    S[pl][o]         = acc[mt][nt][0];
                    S[pl + 1][o]     = acc[mt][nt][1];
                    S[pl][o + 8]     = acc[mt][nt][2];
                    S[pl + 1][o + 8] = acc[mt][nt][3];
                }
            }
        }
        __syncthreads();
        #pragma unroll
        for (int i = 0; i < 2; i++) {
            int idx = tid + i * 256;
            int pl = idx >> 3;           // 0..63 (c8 invariant)
            float4 f0 = *(const float4*)&S[pl][c8 * 8];
            float4 f1 = *(const float4*)&S[pl][c8 * 8 + 4];
            __half2 h[4];
            h[0] = __floats2half2_rn(f0.x + vb[0], f0.y + vb[1]);
            h[1] = __floats2half2_rn(f0.z + vb[2], f0.w + vb[3]);
            h[2] = __floats2half2_rn(f1.x + vb[4], f1.y + vb[5]);
            h[3] = __floats2half2_rn(f1.z + vb[6], f1.w + vb[7]);
            *(uint4*)(vout + (size_t)(pbase + pass * 64 + pl) * 576 + c8 * 8) = *(uint4*)h;
        }
        __syncthreads();
    }
}

// ---------------- K4: build splat record table ----------------
__device__ __forceinline__ void emit_rec(int m, float wt, int yi, int xi) {
    if (yi < 0)          { yi = -yi;        xi = (xi + 512) & 1023; }
    else if (yi >= 512)  { yi = 1024 - yi;  xi = (xi + 512) & 1023; }
    if (yi > 511) yi = 511;
    if (yi < 0)   yi = 0;
    int idx = yi * 1024 + xi;
    int slot = atomicAdd(&g_cnt[idx], 1);
    if (slot < MAXREC) g_rec[(size_t)idx * MAXREC + slot] = make_int2(m, __float_as_int(wt));
}

__global__ __launch_bounds__(256) void k_build(const float* __restrict__ grid) {
    int m = blockIdx.x * 256 + threadIdx.x;
    if (m >= NPTS) return;
    float2 gxy = ((const float2*)grid)[m];
    float px = (gxy.x + 1.0f) * 0.5f * 1023.0f;
    float py = (gxy.y + 1.0f) * 0.5f * 511.0f;
    float fpx = floorf(px), fpy = floorf(py);
    int x0 = (int)fpx, y0 = (int)fpy;
    float fx = px - fpx, fy = py - fpy;
    float wx0 = 1.0f - fx, wy0 = 1.0f - fy;
    int x0w = x0 & 1023, x1w = (x0 + 1) & 1023;
    emit_rec(m, wx0 * wy0, y0,     x0w);
    emit_rec(m, wx0 * fy,  y0 + 1, x0w);
    emit_rec(m, fx  * wy0, y0,     x1w);
    emit_rec(m, fx  * fy,  y0 + 1, x1w);
}

// ---------------- K5: gather + div + bias + GN2 stats (smem-reduced) ------
__global__ __launch_bounds__(256) void k_gather(float* __restrict__ out) {
    int base = blockIdx.x * 256;         // 256 pixels per block
    int tid = threadIdx.x;
    int w = tid >> 5, lane = tid & 31;
    __shared__ float buf[2][64][33];

    const __half2* v0 = (const __half2*)g_vals2h;                 // batch 0
    const __half2* v1 = (const __half2*)(g_vals2h + (size_t)VB);  // batch 1
    float bz0 = g_bias2[2 * lane], bz1 = g_bias2[2 * lane + 1];

    // stats carried in only 2 registers by threads 0..127 (one (b,c) each)
    float st_s = 0.f, st_q = 0.f;
    const float* myrow = (tid < 128) ? &buf[tid >> 6][tid & 63][0] : 0;

    for (int t = 0; t < 8; t++) {
        int pb = base + t * 32;
        for (int jj = 0; jj < 4; jj++) {
            int pp = jj * 8 + w;
            int p = pb + pp;
            int cnt = g_cnt[p];
            if (cnt > MAXREC) cnt = MAXREC;
            const int2* rp = &g_rec[(size_t)p * MAXREC];
            int2 myrec = make_int2(0, 0);
            if (lane < cnt) myrec = rp[lane];
            float a0x = 0.f, a0y = 0.f, a1x = 0.f, a1y = 0.f, den = 0.f;
            for (int r = 0; r < cnt; r++) {
                int rid  = __shfl_sync(0xffffffffu, myrec.x, r);
                float wt = __int_as_float(__shfl_sync(0xffffffffu, myrec.y, r));
                float2 f0 = __half22float2(v0[(size_t)rid * 32 + lane]);
                float2 f1 = __half22float2(v1[(size_t)rid * 32 + lane]);
                a0x += wt * f0.x; a0y += wt * f0.y;
                a1x += wt * f1.x; a1y += wt * f1.y;
                den += wt;
            }
            float rd = 1.0f / fmaxf(den, 1e-8f);
            buf[0][2 * lane][pp]     = a0x * rd + bz0;
            buf[0][2 * lane + 1][pp] = a0y * rd + bz1;
            buf[1][2 * lane][pp]     = a1x * rd + bz0;
            buf[1][2 * lane + 1][pp] = a1y * rd + bz1;
        }
        __syncthreads();
        #pragma unroll
        for (int b = 0; b < 2; b++) {
            #pragma unroll
            for (int r = 0; r < 8; r++) {
                int c = r * 8 + w;
                out[((size_t)(b * 64 + c)) * HW + pb + lane] = buf[b][c][lane];
            }
        }
        // GN2 stats: threads 0..127 each reduce their (b,c) row (stride 33
        // floats => (tid+j) mod 32 banks: conflict-free)
        if (tid < 128) {
            #pragma unroll 8
            for (int j = 0; j < 32; j++) {
                float v = myrow[j];
                st_s += v; st_q += v * v;
            }
        }
        __syncthreads();
    }
    if (tid < 128) {
        atomicAdd(&g_gn2sum[tid], st_s);
        atomicAdd(&g_gn2ssq[tid], st_q);
    }
}

// ---------------- K6: GN2 + exact GELU ----------------
__global__ __launch_bounds__(256) void k_final(float* __restrict__ out,
                                               const float* __restrict__ gamma2,
                                               const float* __restrict__ beta2) {
    size_t i4 = (size_t)blockIdx.x * 256 + threadIdx.x;   // float4 index
    int bc = (int)(i4 >> 17);            // 131072 float4 per (b,c) row
    int b = bc >> 6, c = bc & 63;
    int g = c >> 1;                      // 2 channels per group
    float S = g_gn2sum[b * 64 + 2 * g] + g_gn2sum[b * 64 + 2 * g + 1];
    float Q = g_gn2ssq[b * 64 + 2 * g] + g_gn2ssq[b * 64 + 2 * g + 1];
    float mu  = S * (1.0f / 1048576.0f);
    float var = Q * (1.0f / 1048576.0f) - mu * mu;
    float sc = rsqrtf(var + 1e-5f) * gamma2[c];
    float sh = beta2[c] - mu * sc;
    float4 v = ((float4*)out)[i4];
    float t;
    t = v.x * sc + sh; v.x = 0.5f * t * (1.0f + erff(t * 0.70710678f));
    t = v.y * sc + sh; v.y = 0.5f * t * (1.0f + erff(t * 0.70710678f));
    t = v.z * sc + sh; v.z = 0.5f * t * (1.0f + erff(t * 0.70710678f));
    t = v.w * sc + sh; v.w = 0.5f * t * (1.0f + erff(t * 0.70710678f));
    ((float4*)out)[i4] = v;
}

// ---------------- launch ----------------
extern "C" void kernel_launch(void* const* d_in, const int* in_sizes, int n_in,
                              void* d_out, int out_size) {
    const float* x          = (const float*)d_in[0];
    const float* grid       = (const float*)d_in[1];
    const float* gamma1     = (const float*)d_in[2];
    const float* beta1      = (const float*)d_in[3];
    const float* w_conv     = (const float*)d_in[4];
    const float* splat_bias = (const float*)d_in[5];
    const float* w_post     = (const float*)d_in[6];
    const float* b_post     = (const float*)d_in[7];
    const float* gamma2     = (const float*)d_in[8];
    const float* beta2      = (const float*)d_in[9];
    float* out = (float*)d_out;

    cudaFuncSetAttribute(k_gemm, cudaFuncAttributeMaxDynamicSharedMemorySize,
                         GEMM_SMEM);

    k_zero<<<2048, 256>>>();
    k_gn1split<<<dim3(256, 4), 256>>>(x);
    k_prep<<<576, 128>>>(w_conv, w_post, gamma1, beta1, splat_bias, b_post);
    k_gemm<<<dim3(9, 512, 2), 256, GEMM_SMEM>>>();
    k_build<<<4608, 256>>>(grid);
    k_gather<<<2048, 256>>>(out);
    k_final<<<65536, 256>>>(out, gamma2, beta2);
}